// round 7
// baseline (speedup 1.0000x reference)
#include <cuda_runtime.h>
#include <cstdint>

#define BB 16
#define DD 512
#define TT 4096

// recurrence: 16 clusters (=batches) x 8 CTAs (=64-col slices) x 128 threads
#define JPC 64
#define WT_STRIDE 516                 // ≡4 (mod 32): conflict-free LDS.128
// smem float offsets
#define MBAR_OFF 0                    // 8 bytes (uint64 mbarrier)
#define RED_OFF  2                    // [64]
#define FEAT_OFF 68                   // [2][512], 16B aligned
#define WT_OFF   (FEAT_OFF + 2 * DD)  // 1092, 16B aligned
#define SMEM_REC_FLOATS (WT_OFF + JPC * WT_STRIDE)
#define SMEM_REC_BYTES (SMEM_REC_FLOATS * 4)

// resbuf[b][i][t]  (128 MB) static scratch
__device__ float g_resbuf[(size_t)BB * DD * TT];

__device__ __forceinline__ uint32_t smem_u32(const void* p) {
    uint32_t a;
    asm("{ .reg .u64 t; cvta.to.shared.u64 t, %1; cvt.u32.u64 %0, t; }" : "=r"(a) : "l"(p));
    return a;
}
__device__ __forceinline__ void st_cluster_f32(uint32_t addr, uint32_t rank, float v) {
    asm volatile("{ .reg .u32 r; mapa.shared::cluster.u32 r, %0, %1; st.shared::cluster.f32 [r], %2; }"
                 :: "r"(addr), "r"(rank), "f"(v) : "memory");
}
__device__ __forceinline__ void mbar_init(uint32_t addr, uint32_t cnt) {
    asm volatile("mbarrier.init.shared.b64 [%0], %1;" :: "r"(addr), "r"(cnt) : "memory");
}
__device__ __forceinline__ void mbar_arrive_remote(uint32_t local_addr, uint32_t rank) {
    asm volatile(
        "{ .reg .u32 r; mapa.shared::cluster.u32 r, %0, %1; "
        "mbarrier.arrive.release.cluster.shared::cluster.b64 _, [r]; }"
        :: "r"(local_addr), "r"(rank) : "memory");
}
__device__ __forceinline__ void mbar_wait_parity(uint32_t addr, uint32_t parity) {
    asm volatile(
        "{ .reg .pred P;\n\t"
        "WL_%=: mbarrier.try_wait.parity.acquire.cluster.shared::cta.b64 P, [%0], %1, 0x989680;\n\t"
        "@P bra WD_%=;\n\t"
        "bra WL_%=;\n\t"
        "WD_%=: }"
        :: "r"(addr), "r"(parity) : "memory");
}
__device__ __forceinline__ void cluster_sync_() {
    asm volatile("barrier.cluster.arrive.aligned;" ::: "memory");
    asm volatile("barrier.cluster.wait.aligned;" ::: "memory");
}

// ncu slot-shifter: with launch order [dummy, rec, dummy, proj] per call,
// the profiler's "-s 5 -c 1" capture (launch #6) lands on rec_kernel.
__global__ void dummy_kernel() {}

// ============================================================================
// Recurrence, ordering "C" (bit-exact, verified rounds 5/6):
// per element: h0 = fma-chain k=0..255 (single fp32 acc, ascending k),
//              h1 = fma-chain k=256..511, s = h0 + h1, v = clip(4*(s+x)).
//
// Sync (new this round): per-CTA mbarrier, 512 expected arrivals per phase.
// Producers (h0 threads) push v to all 8 ranks via st.shared::cluster, then
// release-arrive at each rank's mbarrier. Consumers acquire-wait on parity
// at the loop top. No barrier.cluster in the loop -> no ~450cyc wait, no
// CCTL.IVALL L1 flush. Race-free: writes to buffer cur(t) (by ranks at step
// t+1) are gated on phase-t completion, which requires every rank's chain
// (i.e., every read of cur(t)) to have finished.
// ============================================================================
__global__ void __cluster_dims__(8, 1, 1) __launch_bounds__(128, 1)
rec_kernel(const float* __restrict__ x, const float* __restrict__ W) {
    extern __shared__ float sm[];
    float* red   = sm + RED_OFF;     // [64]
    float* feats = sm + FEAT_OFF;    // [2][512]
    float* Wt    = sm + WT_OFF;      // [64][516]: Wt[col][k]

    const int tid  = threadIdx.x;
    const int rank = blockIdx.x & 7;
    const int b    = blockIdx.x >> 3;
    const int col  = tid & 63;
    const int h    = tid >> 6;        // 0 or 1 (which 256-half)
    const int j0   = rank * JPC;
    const int gj   = j0 + col;

    const uint32_t sm_u32    = smem_u32(sm);
    const uint32_t mbar_addr = sm_u32 + MBAR_OFF * 4;
    const uint32_t feats_u32 = sm_u32 + FEAT_OFF * 4;

    if (tid == 0) mbar_init(mbar_addr, 512);   // 64 h0-threads x 8 ranks

    // SMEM W slice transposed: Wt[col][k] = W[k][j0+col]  (one-time)
    for (int idx = tid; idx < DD * JPC; idx += 128) {
        int k  = idx >> 6;
        int jl = idx & 63;
        Wt[jl * WT_STRIDE + k] = W[(size_t)k * DD + j0 + jl];
    }
    for (int idx = tid; idx < 2 * DD; idx += 128) feats[idx] = 0.f;

    // Register-pinned W: even 4-k groups of this thread's half.
    float wreg[128];
#pragma unroll
    for (int g2 = 0; g2 < 32; g2++) {
#pragma unroll
        for (int j = 0; j < 4; j++)
            wreg[g2 * 4 + j] = W[(size_t)(h * 256 + g2 * 8 + j) * DD + gj];
    }

    const float4* __restrict__ wr4 =
        (const float4*)(Wt + col * WT_STRIDE + h * 256);
    const float* __restrict__ xp = x + ((size_t)b * DD + gj) * TT;
    float* __restrict__ rp = g_resbuf + ((size_t)b * DD + gj) * TT;

    __syncthreads();
    cluster_sync_();   // mbar init + feat zero + Wt visible cluster-wide

    for (int t = 0; t < TT; t++) {
        // wait for all ranks' step-(t-1) writes into feats[t&1]
        if (t) mbar_wait_parity(mbar_addr, (t - 1) & 1);

        float xv = 0.f;
        if (h == 0) xv = __ldg(xp + t);   // consumed ~1000 cyc later

        // 256-long single-accumulator fma chain, ascending k.
        const float4* __restrict__ f4 =
            (const float4*)(feats + (t & 1) * DD) + h * 64;
        float a = 0.f;
#pragma unroll
        for (int g2 = 0; g2 < 32; g2++) {
            const float4 f0 = f4[2 * g2];              // even group: W in regs
            a = fmaf(f0.x, wreg[4 * g2 + 0], a);
            a = fmaf(f0.y, wreg[4 * g2 + 1], a);
            a = fmaf(f0.z, wreg[4 * g2 + 2], a);
            a = fmaf(f0.w, wreg[4 * g2 + 3], a);
            const float4 f1 = f4[2 * g2 + 1];          // odd group: W in SMEM
            const float4 w1 = wr4[2 * g2 + 1];
            a = fmaf(f1.x, w1.x, a);
            a = fmaf(f1.y, w1.y, a);
            a = fmaf(f1.z, w1.z, a);
            a = fmaf(f1.w, w1.w, a);
        }

        if (h == 1) red[col] = a;
        __syncthreads();

        if (h == 0) {
            const float s = a + red[col];            // h0 + h1 (exact order)
            const float v = fminf(1.f, fmaxf(-1.f, 4.f * (s + xv)));
            rp[t] = v;
            if (t < TT - 1) {
                const uint32_t dst =
                    feats_u32 + (uint32_t)((((t & 1) ^ 1)) * DD + gj) * 4u;
#pragma unroll
                for (int rr = 0; rr < 8; rr++)
                    st_cluster_f32(dst, (uint32_t)rr, v);
#pragma unroll
                for (int rr = 0; rr < 8; rr++)
                    mbar_arrive_remote(mbar_addr, (uint32_t)rr);
            }
        }
    }
    cluster_sync_();   // keep SMEM alive until all ranks are done
}

// ============================================================================
// Projection: out[b][o][t] = sum_i lin_w[o][i] * resbuf[b][i][t] + lin_b[o]
// 128x128 tile, 8x8 microtile. Microtile remapped to {q, 64+q} float4 pairs
// -> conflict-free LDS.128 phases (was 2-way conflicted; L1 was 82% busy).
// ============================================================================
__global__ void __launch_bounds__(256) proj_kernel(
    const float* __restrict__ lin_w, const float* __restrict__ lin_b,
    float* __restrict__ out) {

    const float* rb = g_resbuf;
    const int b  = blockIdx.z;
    const int o0 = blockIdx.y * 128;
    const int t0 = blockIdx.x * 128;

    __shared__ float As[8][128];
    __shared__ float Bs[8][128];

    const int tid = threadIdx.x;
    const int tx  = tid & 15;    // t-quad
    const int ty  = tid >> 4;    // o-quad

    float acc[8][8];
#pragma unroll
    for (int r = 0; r < 8; r++)
#pragma unroll
        for (int c = 0; c < 8; c++) acc[r][c] = 0.f;

    const int lo   = tid >> 1;
    const int half = (tid & 1) * 4;
    const int brow = tid >> 5;
    const int bc4  = (tid & 31) * 4;

    for (int k0 = 0; k0 < DD; k0 += 8) {
        float4 av = *(const float4*)&lin_w[(size_t)(o0 + lo) * DD + k0 + half];
        float4 bv = *(const float4*)&rb[((size_t)b * DD + k0 + brow) * TT + t0 + bc4];
        __syncthreads();
        As[half + 0][lo] = av.x; As[half + 1][lo] = av.y;
        As[half + 2][lo] = av.z; As[half + 3][lo] = av.w;
        *(float4*)&Bs[brow][bc4] = bv;
        __syncthreads();

#pragma unroll
        for (int ii = 0; ii < 8; ii++) {
            float4 a0 = *(const float4*)&As[ii][ty * 4];
            float4 a1 = *(const float4*)&As[ii][64 + ty * 4];
            float4 b0 = *(const float4*)&Bs[ii][tx * 4];
            float4 b1 = *(const float4*)&Bs[ii][64 + tx * 4];
            float a[8]  = {a0.x, a0.y, a0.z, a0.w, a1.x, a1.y, a1.z, a1.w};
            float bb[8] = {b0.x, b0.y, b0.z, b0.w, b1.x, b1.y, b1.z, b1.w};
#pragma unroll
            for (int r = 0; r < 8; r++)
#pragma unroll
                for (int c = 0; c < 8; c++)
                    acc[r][c] = fmaf(a[r], bb[c], acc[r][c]);
        }
    }

#pragma unroll
    for (int g = 0; g < 2; g++) {
#pragma unroll
        for (int r = 0; r < 4; r++) {
            const int o  = o0 + g * 64 + ty * 4 + r;
            const int ar = g * 4 + r;
            const float bias = lin_b[o];
            float4 v0, v1;
            v0.x = acc[ar][0] + bias; v0.y = acc[ar][1] + bias;
            v0.z = acc[ar][2] + bias; v0.w = acc[ar][3] + bias;
            v1.x = acc[ar][4] + bias; v1.y = acc[ar][5] + bias;
            v1.z = acc[ar][6] + bias; v1.w = acc[ar][7] + bias;
            float* op = &out[((size_t)b * DD + o) * TT + t0];
            *(float4*)(op + tx * 4)      = v0;
            *(float4*)(op + 64 + tx * 4) = v1;
        }
    }
}

extern "C" void kernel_launch(void* const* d_in, const int* in_sizes, int n_in,
                              void* d_out, int out_size) {
    const float* x     = (const float*)d_in[0];
    const float* W     = (const float*)d_in[1];
    const float* lin_w = (const float*)d_in[2];
    const float* lin_b = (const float*)d_in[3];
    float* out = (float*)d_out;

    cudaFuncSetAttribute(rec_kernel,
                         cudaFuncAttributeMaxDynamicSharedMemorySize,
                         SMEM_REC_BYTES);
    // launch order [dummy, rec, dummy, proj]: ncu's 6th launch = rec_kernel
    dummy_kernel<<<1, 32>>>();
    rec_kernel<<<dim3(BB * 8), 128, SMEM_REC_BYTES>>>(x, W);
    dummy_kernel<<<1, 32>>>();
    proj_kernel<<<dim3(TT / 128, DD / 128, BB), 256>>>(lin_w, lin_b, out);
}

// round 8
// speedup vs baseline: 2.7132x; 2.7132x over previous
#include <cuda_runtime.h>
#include <cstdint>

#define BB 16
#define DD 512
#define TT 4096

// recurrence: 16 clusters (=batches) x 8 CTAs (=64-col slices) x 128 threads
#define JPC 64
// W layout: 64 k-groups of 4; groups with g%4!=3 live in regs (192 floats),
// g%4==3 (16 groups) live in SMEM: Wt[col][16*4], padded stride 68.
#define WT_STRIDE 68
#define RED_OFF  0                    // [64]
#define FEAT_OFF 64                   // [2][512], 16B aligned
#define WT_OFF   (FEAT_OFF + 2 * DD)  // 1088, 16B aligned
#define SMEM_REC_FLOATS (WT_OFF + JPC * WT_STRIDE)
#define SMEM_REC_BYTES (SMEM_REC_FLOATS * 4)

// resbuf[b][i][t]  (128 MB) static scratch
__device__ float g_resbuf[(size_t)BB * DD * TT];

__device__ __forceinline__ uint32_t smem_u32(const void* p) {
    uint32_t a;
    asm("{ .reg .u64 t; cvta.to.shared.u64 t, %1; cvt.u32.u64 %0, t; }" : "=r"(a) : "l"(p));
    return a;
}
__device__ __forceinline__ void st_cluster_f32(uint32_t addr, uint32_t rank, float v) {
    asm volatile("{ .reg .u32 r; mapa.shared::cluster.u32 r, %0, %1; st.shared::cluster.f32 [r], %2; }"
                 :: "r"(addr), "r"(rank), "f"(v) : "memory");
}
__device__ __forceinline__ void cluster_sync_() {
    asm volatile("barrier.cluster.arrive.aligned;" ::: "memory");
    asm volatile("barrier.cluster.wait.aligned;" ::: "memory");
}

// ============================================================================
// Recurrence body, ordering "C" (bit-exact, verified rounds 5-7):
// per element: h0 = fma-chain k=0..255 (single fp32 acc, ascending k),
//              h1 = fma-chain k=256..511, s = h0 + h1, v = clip(4*(s+x)).
// Sync: cluster.sync per step (R6 structure; R7's mbarrier fanout regressed).
// W: 3/4 in registers (192/thread), 1/4 in SMEM -> crossbar ~32KB/step.
// NSTEPS is a template param so a short "probe" clone can be profiled by ncu.
// ============================================================================
template <int NSTEPS>
__device__ __forceinline__ void rec_body(const float* __restrict__ x,
                                         const float* __restrict__ W) {
    extern __shared__ float sm[];
    float* red   = sm + RED_OFF;     // [64]
    float* feats = sm + FEAT_OFF;    // [2][512]
    float* Wt    = sm + WT_OFF;      // [64][68]: SMEM-resident quarter of W

    const int tid  = threadIdx.x;
    const int rank = blockIdx.x & 7;
    const int b    = blockIdx.x >> 3;
    const int col  = tid & 63;
    const int h    = tid >> 6;        // 0 or 1 (which 256-half)
    const int j0   = rank * JPC;
    const int gj   = j0 + col;

    // SMEM quarter: Wt[col][q*4+j] = W[h'? no: k = 16q+12+j ... ] -- we store
    // group g=4q+3 (k = h*256 + (4q+3)*4 + j) transposed per column.
    // Loader: iterate (col, q, j).
    for (int idx = tid; idx < JPC * 16 * 4; idx += 128) {
        int jl = idx >> 6;            // 0..63 col
        int q  = (idx >> 2) & 15;     // 0..15
        int jj = idx & 3;
        // this CTA's h is per-thread; SMEM must hold BOTH halves' quarters?
        // No: threads of half h only read their own half's groups. But the
        // shared tile is shared by both halves -> store both: use 2 tiles?
        // Simpler: Wt holds k-groups for BOTH halves: col-major over 64 cols,
        // 16 groups of 4 floats = this covers one half only. We need per-half.
        // Resolve: halves read disjoint k; keep one tile per half stacked in
        // the same 68-stride rows: row = col, entries [q*4+jj] for h=0 and
        // we fold h into q via +?? -- instead allocate h in the unused pad:
        // entries 0..63 = h0 groups, stride region too small. Use col+64*h? 
        // -> handled below by separate loader loop; this loop loads h0 part.
        int k = (4 * q + 3) * 4 + jj;     // h0 half
        Wt[jl * WT_STRIDE + q * 4 + jj] = W[(size_t)k * DD + j0 + jl];
    }
    // NOTE: h1 threads read the SAME Wt slots? NO -- different k. We must
    // keep both. Rather than a second tile, h1's SMEM quarter is ALSO pinned
    // to registers is impossible (192 cap). Solution: second tile region.
    __syncthreads();

    // Second tile for h1 quarter, placed right after (offset JPC*WT_STRIDE/2?)
    // -- implemented cleanly below with a dedicated pointer.
    float* Wt1 = Wt + 64;   // unused tail of each 68-row? only 4 floats pad.
    // Not enough; instead interleave: we gave WT_STRIDE=68 = 64 (h0 16x4) + 4.
    // Insufficient for h1. Fallback: h1 quarter ALSO from registers?
    // -> Final resolution (compile-time): pin 192 regs for g%4!=3 of own half
    //    and ALSO 64 regs... too many. Instead: both halves' SMEM quarters
    //    stacked as rows 64..127: Wt[(64+col)][..] requires 128*68 floats.
    (void)Wt1;

    // ---- actual W-register pinning: own half's groups g with g%4 != 3 ----
    float wreg[192];
#pragma unroll
    for (int q = 0; q < 16; q++) {
#pragma unroll
        for (int m = 0; m < 3; m++) {          // sub-groups g = 4q+m
#pragma unroll
            for (int j = 0; j < 4; j++) {
                int k = h * 256 + (4 * q + m) * 4 + j;
                wreg[(q * 3 + m) * 4 + j] = W[(size_t)k * DD + gj];
            }
        }
    }

    // ---- h1 SMEM quarter lives in rows 64..127 (see SMEM sizing) ----
    float* WtH = sm + WT_OFF;   // rows: col + 64*h
    for (int idx = tid; idx < JPC * 16 * 4; idx += 128) {
        int jl = idx >> 6;
        int q  = (idx >> 2) & 15;
        int jj = idx & 3;
        int k  = 256 + (4 * q + 3) * 4 + jj;   // h1 half
        WtH[(64 + jl) * WT_STRIDE + q * 4 + jj] = W[(size_t)k * DD + j0 + jl];
    }

    for (int idx = tid; idx < 2 * DD; idx += 128) feats[idx] = 0.f;

    const uint32_t feats_u32 = smem_u32(feats);
    const float4* __restrict__ wq4 =
        (const float4*)(WtH + (h * 64 + col) * WT_STRIDE);  // 16 groups
    const float* __restrict__ xp = x + ((size_t)b * DD + gj) * TT;
    float* __restrict__ rp = g_resbuf + ((size_t)b * DD + gj) * TT;

    __syncthreads();
    cluster_sync_();

    for (int t = 0; t < NSTEPS; t++) {
        const int cur = t & 1;
        const int nxt = cur ^ 1;

        float xv = 0.f;
        if (h == 0) xv = __ldg(xp + t);

        // 256-long single-accumulator fma chain, ascending k.
        // groups 4q+0..2 from regs, 4q+3 from SMEM. Order == ascending k.
        const float4* __restrict__ f4 =
            (const float4*)(feats + cur * DD) + h * 64;
        float a = 0.f;
#pragma unroll
        for (int q = 0; q < 16; q++) {
#pragma unroll
            for (int m = 0; m < 3; m++) {
                const float4 f = f4[4 * q + m];
                const int wb = (q * 3 + m) * 4;
                a = fmaf(f.x, wreg[wb + 0], a);
                a = fmaf(f.y, wreg[wb + 1], a);
                a = fmaf(f.z, wreg[wb + 2], a);
                a = fmaf(f.w, wreg[wb + 3], a);
            }
            const float4 f = f4[4 * q + 3];
            const float4 w = wq4[q];
            a = fmaf(f.x, w.x, a);
            a = fmaf(f.y, w.y, a);
            a = fmaf(f.z, w.z, a);
            a = fmaf(f.w, w.w, a);
        }

        if (h == 1) red[col] = a;
        __syncthreads();

        if (h == 0) {
            const float s = a + red[col];            // h0 + h1 (exact order)
            const float v = fminf(1.f, fmaxf(-1.f, 4.f * (s + xv)));
            rp[t] = v;
            const uint32_t dst = feats_u32 + (uint32_t)(nxt * DD + gj) * 4u;
#pragma unroll
            for (int rr = 0; rr < 8; rr++) st_cluster_f32(dst, (uint32_t)rr, v);
        }
        cluster_sync_();
    }
}

__global__ void __cluster_dims__(8, 1, 1) __launch_bounds__(128, 1)
rec_kernel(const float* __restrict__ x, const float* __restrict__ W) {
    rec_body<TT>(x, W);
}

// 12-step probe clone: same code path, tiny runtime; exists so ncu's fixed
// capture slot lands on the recurrence loop and yields its SASS/stalls.
__global__ void __cluster_dims__(8, 1, 1) __launch_bounds__(128, 1)
rec_probe_kernel(const float* __restrict__ x, const float* __restrict__ W) {
    rec_body<12>(x, W);
}

// SMEM sizing: rows 0..127 of Wt (both halves) => redefine total here.
#undef SMEM_REC_FLOATS
#define SMEM_REC_FLOATS (WT_OFF + 128 * WT_STRIDE)
#undef SMEM_REC_BYTES
#define SMEM_REC_BYTES (SMEM_REC_FLOATS * 4)

// ============================================================================
// Projection: out[b][o][t] = sum_i lin_w[o][i] * resbuf[b][i][t] + lin_b[o]
// 128x128 tile, 8x8 microtile split as {q, 64+q} float4 pairs (conflict-free).
// ============================================================================
__global__ void __launch_bounds__(256) proj_kernel(
    const float* __restrict__ lin_w, const float* __restrict__ lin_b,
    float* __restrict__ out) {

    const float* rb = g_resbuf;
    const int b  = blockIdx.z;
    const int o0 = blockIdx.y * 128;
    const int t0 = blockIdx.x * 128;

    __shared__ float As[8][128];
    __shared__ float Bs[8][128];

    const int tid = threadIdx.x;
    const int tx  = tid & 15;
    const int ty  = tid >> 4;

    float acc[8][8];
#pragma unroll
    for (int r = 0; r < 8; r++)
#pragma unroll
        for (int c = 0; c < 8; c++) acc[r][c] = 0.f;

    const int lo   = tid >> 1;
    const int half = (tid & 1) * 4;
    const int brow = tid >> 5;
    const int bc4  = (tid & 31) * 4;

    for (int k0 = 0; k0 < DD; k0 += 8) {
        float4 av = *(const float4*)&lin_w[(size_t)(o0 + lo) * DD + k0 + half];
        float4 bv = *(const float4*)&rb[((size_t)b * DD + k0 + brow) * TT + t0 + bc4];
        __syncthreads();
        As[half + 0][lo] = av.x; As[half + 1][lo] = av.y;
        As[half + 2][lo] = av.z; As[half + 3][lo] = av.w;
        *(float4*)&Bs[brow][bc4] = bv;
        __syncthreads();

#pragma unroll
        for (int ii = 0; ii < 8; ii++) {
            float4 a0 = *(const float4*)&As[ii][ty * 4];
            float4 a1 = *(const float4*)&As[ii][64 + ty * 4];
            float4 b0 = *(const float4*)&Bs[ii][tx * 4];
            float4 b1 = *(const float4*)&Bs[ii][64 + tx * 4];
            float a[8]  = {a0.x, a0.y, a0.z, a0.w, a1.x, a1.y, a1.z, a1.w};
            float bb[8] = {b0.x, b0.y, b0.z, b0.w, b1.x, b1.y, b1.z, b1.w};
#pragma unroll
            for (int r = 0; r < 8; r++)
#pragma unroll
                for (int c = 0; c < 8; c++)
                    acc[r][c] = fmaf(a[r], bb[c], acc[r][c]);
        }
    }

#pragma unroll
    for (int g = 0; g < 2; g++) {
#pragma unroll
        for (int r = 0; r < 4; r++) {
            const int o  = o0 + g * 64 + ty * 4 + r;
            const int ar = g * 4 + r;
            const float bias = lin_b[o];
            float4 v0, v1;
            v0.x = acc[ar][0] + bias; v0.y = acc[ar][1] + bias;
            v0.z = acc[ar][2] + bias; v0.w = acc[ar][3] + bias;
            v1.x = acc[ar][4] + bias; v1.y = acc[ar][5] + bias;
            v1.z = acc[ar][6] + bias; v1.w = acc[ar][7] + bias;
            float* op = &out[((size_t)b * DD + o) * TT + t0];
            *(float4*)(op + tx * 4)      = v0;
            *(float4*)(op + 64 + tx * 4) = v1;
        }
    }
}

extern "C" void kernel_launch(void* const* d_in, const int* in_sizes, int n_in,
                              void* d_out, int out_size) {
    const float* x     = (const float*)d_in[0];
    const float* W     = (const float*)d_in[1];
    const float* lin_w = (const float*)d_in[2];
    const float* lin_b = (const float*)d_in[3];
    float* out = (float*)d_out;

    cudaFuncSetAttribute(rec_kernel,
                         cudaFuncAttributeMaxDynamicSharedMemorySize,
                         SMEM_REC_BYTES);
    cudaFuncSetAttribute(rec_probe_kernel,
                         cudaFuncAttributeMaxDynamicSharedMemorySize,
                         SMEM_REC_BYTES);

    // order [rec, proj, probe, probe]: for 1-3 harness-internal extra
    // launches, ncu's fixed capture slot lands on a recurrence-body kernel.
    rec_kernel<<<dim3(BB * 8), 128, SMEM_REC_BYTES>>>(x, W);
    proj_kernel<<<dim3(TT / 128, DD / 128, BB), 256>>>(lin_w, lin_b, out);
    rec_probe_kernel<<<dim3(BB * 8), 128, SMEM_REC_BYTES>>>(x, W);
    rec_probe_kernel<<<dim3(BB * 8), 128, SMEM_REC_BYTES>>>(x, W);
}

// round 9
// speedup vs baseline: 3.2173x; 1.1858x over previous
#include <cuda_runtime.h>
#include <cstdint>

#define BB 16
#define DD 512
#define TT 4096

// recurrence: 16 clusters (=batches) x 4 CTAs (=128-col slices) x 256 threads
#define CLU 4
#define TPC 256
#define CPC 128
// smem layout (float offsets)
#define REDA_OFF 0
#define REDB_OFF 128
#define FEAT_OFF 256                       // [2][512]
#define WT_OFF   (FEAT_OFF + 2 * DD)       // 1280
#define WT_STRIDE 68                       // 17 float4: conflict-free LDS.128
#define SMEM_REC_FLOATS (WT_OFF + 256 * WT_STRIDE)   // 18688
#define SMEM_REC_BYTES (SMEM_REC_FLOATS * 4)         // 74752

// resbuf[b][i][t]  (128 MB) static scratch
__device__ float g_resbuf[(size_t)BB * DD * TT];

__device__ __forceinline__ uint32_t smem_u32(const void* p) {
    uint32_t a;
    asm("{ .reg .u64 t; cvta.to.shared.u64 t, %1; cvt.u32.u64 %0, t; }" : "=r"(a) : "l"(p));
    return a;
}
__device__ __forceinline__ void st_cluster_f32(uint32_t addr, uint32_t rank, float v) {
    asm volatile("{ .reg .u32 r; mapa.shared::cluster.u32 r, %0, %1; st.shared::cluster.f32 [r], %2; }"
                 :: "r"(addr), "r"(rank), "f"(v) : "memory");
}
__device__ __forceinline__ void cluster_arrive_() {
    asm volatile("barrier.cluster.arrive.aligned;" ::: "memory");
}
__device__ __forceinline__ void cluster_wait_() {
    asm volatile("barrier.cluster.wait.aligned;" ::: "memory");
}
__device__ __forceinline__ void cluster_sync_() {
    cluster_arrive_(); cluster_wait_();
}

// ============================================================================
// Recurrence body, ordering "C" (bit-exact, verified rounds 5-8):
// per element: h0 = fma-chain k=0..255 (single fp32 acc, ascending k),
//              h1 = fma-chain k=256..511, s = h0 + h1, v = clip(4*(s+x)).
//
// vs R8: cluster 8->4 (less barrier skew), split arrive/wait with STG and
// x-prefetch in the overlap window, producer duties split across halves
// (h0 pushes ranks 0-1, h1 pushes ranks 2-3).
// W: 3/4 in regs (192/thread, own half, groups 4q+{0,1,2}), 1/4 in SMEM
// (groups 4q+3, both halves, rows = h*128+col, stride 68).
// ============================================================================
template <int NSTEPS>
__device__ __forceinline__ void rec_body(const float* __restrict__ x,
                                         const float* __restrict__ W) {
    extern __shared__ float sm[];
    float* redA  = sm + REDA_OFF;    // [128] h0 partials
    float* redB  = sm + REDB_OFF;    // [128] h1 partials
    float* feats = sm + FEAT_OFF;    // [2][512]
    float* Wt    = sm + WT_OFF;      // [256][68]

    const int tid  = threadIdx.x;
    const int rank = blockIdx.x & 3;
    const int b    = blockIdx.x >> 2;
    const int col  = tid & 127;
    const int h    = tid >> 7;        // 0 or 1 (which 256-half)
    const int j0   = rank * CPC;
    const int gj   = j0 + col;

    // SMEM quarter (groups g=4q+3 of both halves), coalesced over columns
    for (int e = tid; e < 256 * 64; e += TPC) {
        int colr = e & 127;
        int j    = (e >> 7) & 3;
        int q    = (e >> 9) & 15;
        int hr   = e >> 13;
        int k    = hr * 256 + 16 * q + 12 + j;
        Wt[(hr * 128 + colr) * WT_STRIDE + q * 4 + j] =
            W[(size_t)k * DD + j0 + colr];
    }
    for (int e = tid; e < 2 * DD; e += TPC) feats[e] = 0.f;

    // Register-pinned 3/4: own half, groups g=4q+m (m=0..2)
    float wreg[192];
#pragma unroll
    for (int q = 0; q < 16; q++)
#pragma unroll
        for (int m = 0; m < 3; m++)
#pragma unroll
            for (int j = 0; j < 4; j++) {
                int k = h * 256 + 16 * q + 4 * m + j;
                wreg[(q * 3 + m) * 4 + j] = W[(size_t)k * DD + gj];
            }

    const uint32_t feats_u32 = smem_u32(feats);
    const float4* __restrict__ wq4 =
        (const float4*)(Wt + (h * 128 + col) * WT_STRIDE);   // 16 groups
    const float* __restrict__ xp = x + ((size_t)b * DD + gj) * TT;
    float* __restrict__ rp = g_resbuf + ((size_t)b * DD + gj) * TT;

    float xv_next = __ldg(xp);    // x for t=0

    __syncthreads();
    cluster_sync_();              // feats/Wt visible cluster-wide

    for (int t = 0; t < NSTEPS; t++) {
        if (t) cluster_wait_();   // completes phase t-1 (arrive at end of t-1)
        const float xv = xv_next;

        // 256-long single-accumulator fma chain, ascending k.
        const float4* __restrict__ f4 =
            (const float4*)(feats + (t & 1) * DD) + h * 64;
        float a = 0.f;
#pragma unroll
        for (int q = 0; q < 16; q++) {
#pragma unroll
            for (int m = 0; m < 3; m++) {
                const float4 f = f4[4 * q + m];
                const int wb = (q * 3 + m) * 4;
                a = fmaf(f.x, wreg[wb + 0], a);
                a = fmaf(f.y, wreg[wb + 1], a);
                a = fmaf(f.z, wreg[wb + 2], a);
                a = fmaf(f.w, wreg[wb + 3], a);
            }
            const float4 f = f4[4 * q + 3];
            const float4 w = wq4[q];
            a = fmaf(f.x, w.x, a);
            a = fmaf(f.y, w.y, a);
            a = fmaf(f.z, w.z, a);
            a = fmaf(f.w, w.w, a);
        }

        if (h == 0) redA[col] = a; else redB[col] = a;
        __syncthreads();

        const float s = redA[col] + redB[col];       // h0 + h1 (exact order)
        const float v = fminf(1.f, fmaxf(-1.f, 4.f * (s + xv)));

        if (t < NSTEPS - 1) {
            // broadcast to this half's two ranks, then arrive (release)
            const uint32_t dst =
                feats_u32 + (uint32_t)((((t & 1) ^ 1)) * DD + gj) * 4u;
            st_cluster_f32(dst, (uint32_t)(2 * h), v);
            st_cluster_f32(dst, (uint32_t)(2 * h + 1), v);
            cluster_arrive_();
            // overlap window: non-critical work while peers arrive
            if (h == 0) rp[t] = v;
            xv_next = __ldg(xp + t + 1);
        } else {
            if (h == 0) rp[t] = v;
        }
    }
}

__global__ void __cluster_dims__(CLU, 1, 1) __launch_bounds__(TPC, 1)
rec_kernel(const float* __restrict__ x, const float* __restrict__ W) {
    rec_body<TT>(x, W);
}

// 12-step probe clone: lands in ncu's fixed capture slot (observed R8).
__global__ void __cluster_dims__(CLU, 1, 1) __launch_bounds__(TPC, 1)
rec_probe_kernel(const float* __restrict__ x, const float* __restrict__ W) {
    rec_body<12>(x, W);
}

// ============================================================================
// Projection: out[b][o][t] = sum_i lin_w[o][i] * resbuf[b][i][t] + lin_b[o]
// 128x128 tile, 8x8 microtile, packed fma.rn.f32x2 (FFMA2): 2x fp32 FMA rate,
// per-lane IEEE rn -> bit-identical to scalar fmaf.
// ============================================================================
typedef unsigned long long u64;
#define FMA2(d, a, bv) \
    asm("fma.rn.f32x2 %0, %1, %2, %0;" : "+l"(d) : "l"(a), "l"(bv))
#define PACK2(o, lo, hi) \
    asm("mov.b64 %0, {%1, %2};" : "=l"(o) : "f"(lo), "f"(hi))
#define UNPACK2(lo, hi, v) \
    asm("mov.b64 {%0, %1}, %2;" : "=f"(lo), "=f"(hi) : "l"(v))

__global__ void __launch_bounds__(256) proj_kernel(
    const float* __restrict__ lin_w, const float* __restrict__ lin_b,
    float* __restrict__ out) {

    const float* rb = g_resbuf;
    const int b  = blockIdx.z;
    const int o0 = blockIdx.y * 128;
    const int t0 = blockIdx.x * 128;

    __shared__ float As[8][128];
    __shared__ float Bs[8][128];

    const int tid = threadIdx.x;
    const int tx  = tid & 15;
    const int ty  = tid >> 4;

    u64 acc2[8][4];
#pragma unroll
    for (int r = 0; r < 8; r++)
#pragma unroll
        for (int c = 0; c < 4; c++) acc2[r][c] = 0ull;

    const int lo   = tid >> 1;
    const int half = (tid & 1) * 4;
    const int brow = tid >> 5;
    const int bc4  = (tid & 31) * 4;

    for (int k0 = 0; k0 < DD; k0 += 8) {
        float4 av = *(const float4*)&lin_w[(size_t)(o0 + lo) * DD + k0 + half];
        float4 bv = *(const float4*)&rb[((size_t)b * DD + k0 + brow) * TT + t0 + bc4];
        __syncthreads();
        As[half + 0][lo] = av.x; As[half + 1][lo] = av.y;
        As[half + 2][lo] = av.z; As[half + 3][lo] = av.w;
        *(float4*)&Bs[brow][bc4] = bv;
        __syncthreads();

#pragma unroll
        for (int ii = 0; ii < 8; ii++) {
            float4 a0 = *(const float4*)&As[ii][ty * 4];
            float4 a1 = *(const float4*)&As[ii][64 + ty * 4];
            float4 b0 = *(const float4*)&Bs[ii][tx * 4];
            float4 b1 = *(const float4*)&Bs[ii][64 + tx * 4];
            u64 b2[4];
            PACK2(b2[0], b0.x, b0.y); PACK2(b2[1], b0.z, b0.w);
            PACK2(b2[2], b1.x, b1.y); PACK2(b2[3], b1.z, b1.w);
            float a[8] = {a0.x, a0.y, a0.z, a0.w, a1.x, a1.y, a1.z, a1.w};
#pragma unroll
            for (int r = 0; r < 8; r++) {
                u64 a2;
                PACK2(a2, a[r], a[r]);
                FMA2(acc2[r][0], a2, b2[0]);
                FMA2(acc2[r][1], a2, b2[1]);
                FMA2(acc2[r][2], a2, b2[2]);
                FMA2(acc2[r][3], a2, b2[3]);
            }
        }
    }

#pragma unroll
    for (int g = 0; g < 2; g++) {
#pragma unroll
        for (int r = 0; r < 4; r++) {
            const int ar = g * 4 + r;
            const int o  = o0 + g * 64 + ty * 4 + r;
            const float bias = lin_b[o];
            float c0, c1, c2, c3, c4, c5, c6, c7;
            UNPACK2(c0, c1, acc2[ar][0]); UNPACK2(c2, c3, acc2[ar][1]);
            UNPACK2(c4, c5, acc2[ar][2]); UNPACK2(c6, c7, acc2[ar][3]);
            float4 v0, v1;
            v0.x = c0 + bias; v0.y = c1 + bias; v0.z = c2 + bias; v0.w = c3 + bias;
            v1.x = c4 + bias; v1.y = c5 + bias; v1.z = c6 + bias; v1.w = c7 + bias;
            float* op = &out[((size_t)b * DD + o) * TT + t0];
            *(float4*)(op + tx * 4)      = v0;
            *(float4*)(op + 64 + tx * 4) = v1;
        }
    }
}

extern "C" void kernel_launch(void* const* d_in, const int* in_sizes, int n_in,
                              void* d_out, int out_size) {
    const float* x     = (const float*)d_in[0];
    const float* W     = (const float*)d_in[1];
    const float* lin_w = (const float*)d_in[2];
    const float* lin_b = (const float*)d_in[3];
    float* out = (float*)d_out;

    cudaFuncSetAttribute(rec_kernel,
                         cudaFuncAttributeMaxDynamicSharedMemorySize,
                         SMEM_REC_BYTES);
    cudaFuncSetAttribute(rec_probe_kernel,
                         cudaFuncAttributeMaxDynamicSharedMemorySize,
                         SMEM_REC_BYTES);

    // order [rec, proj, probe, probe]: ncu's capture slot lands on a probe
    rec_kernel<<<dim3(BB * CLU), TPC, SMEM_REC_BYTES>>>(x, W);
    proj_kernel<<<dim3(TT / 128, DD / 128, BB), 256>>>(lin_w, lin_b, out);
    rec_probe_kernel<<<dim3(BB * CLU), TPC, SMEM_REC_BYTES>>>(x, W);
    rec_probe_kernel<<<dim3(BB * CLU), TPC, SMEM_REC_BYTES>>>(x, W);
}